// round 5
// baseline (speedup 1.0000x reference)
#include <cuda_runtime.h>
#include <cstdint>

#define NPTS 4096
#define DDIM 64
#define LDT 68   // padded smem stride (floats): conflict-free fragment loads

// ---------------- device scratch (zero-init; counters self-reset each launch) ----------------
__device__ float g_partial_sq[64];
__device__ float g_partial_col[64][64];
__device__ float g_c;
__device__ int   g_arrive = 0;
__device__ int   g_done   = 0;
__device__ unsigned int g_flag = 0;

__device__ __forceinline__ uint32_t to_tf32(float f) {
    uint32_t o; asm("cvt.rna.tf32.f32 %0, %1;" : "=r"(o) : "f"(f)); return o;
}

// ---------------- single fused kernel ----------------
// 128x128 tile per CTA, 256 threads = 8 warps (4 row-groups x 2 col-groups).
// Blocks bid<64 additionally compute the global bandwidth reduction.
__global__ __launch_bounds__(256, 2)
void rbf_fused_kernel(const float* __restrict__ X, float* __restrict__ out) {
    extern __shared__ float smem[];
    float* As = smem;                 // [128][LDT] tf32
    float* Bs = smem + 128 * LDT;
    __shared__ float sqa[128], sqb[128];
    __shared__ float red[256];
    __shared__ float colp[8][64];
    __shared__ float s_c;
    __shared__ int   s_last;

    const int tid = threadIdx.x;
    const int wid = tid >> 5, lane = tid & 31;
    const int bid = blockIdx.y * gridDim.x + blockIdx.x;
    const int rowBase = blockIdx.y << 7, colBase = blockIdx.x << 7;

    // ================= phase 0: bandwidth reduction duty (bid < 64) =================
    if (bid < 64) {
        const int rrow = (bid << 6) + (tid >> 2);   // 64 rows per duty-block
        const int q = tid & 3;
        const int warp = wid;

        float v[16];
        const float4* p = (const float4*)(X + (size_t)rrow * DDIM + q * 16);
        float s = 0.f;
#pragma unroll
        for (int i = 0; i < 4; i++) {
            float4 f = p[i];
            v[i * 4 + 0] = f.x; v[i * 4 + 1] = f.y; v[i * 4 + 2] = f.z; v[i * 4 + 3] = f.w;
            s += f.x * f.x + f.y * f.y + f.z * f.z + f.w * f.w;
        }
        red[tid] = s;
        __syncthreads();
#pragma unroll
        for (int off = 128; off > 0; off >>= 1) {
            if (tid < off) red[tid] += red[tid + off];
            __syncthreads();
        }
        if (tid == 0) g_partial_sq[bid] = red[0];

        // column partials: butterfly over rows within warp (strides 4,8,16)
#pragma unroll
        for (int stp = 4; stp <= 16; stp <<= 1)
#pragma unroll
            for (int i = 0; i < 16; i++)
                v[i] += __shfl_xor_sync(0xffffffffu, v[i], stp);
        if (lane < 4) {
#pragma unroll
            for (int i = 0; i < 16; i++) colp[warp][lane * 16 + i] = v[i];
        }
        __syncthreads();
        if (tid < 64) {
            float t = 0.f;
#pragma unroll
            for (int w = 0; w < 8; w++) t += colp[w][tid];
            g_partial_col[bid][tid] = t;
        }
        __threadfence();
        if (tid == 0) {
            int r = atomicAdd(&g_arrive, 1);
            s_last = (r == 63);
        }
        __syncthreads();

        if (s_last) {
            // finalize: fixed-order sums -> deterministic g_c
            if (tid < 64) {
                float cs = 0.f;
#pragma unroll
                for (int b = 0; b < 64; b++) cs += g_partial_col[b][tid];
                red[tid] = cs * cs;
                red[128 + tid] = g_partial_sq[tid];
            }
            __syncthreads();
#pragma unroll
            for (int off = 32; off > 0; off >>= 1) {
                if (tid < off) { red[tid] += red[tid + off]; red[128 + tid] += red[128 + tid + off]; }
                __syncthreads();
            }
            if (tid == 0) {
                // sum(L2) = 2*N*sum(||xi||^2) - 2*||sum xi||^2 (clamp effect negligible)
                float bwsum = 2.f * (float)NPTS * red[128] - 2.f * red[0];
                float bw = bwsum / ((float)NPTS * (float)(NPTS - 1));
                g_c = 1.4426950408889634f / (4.f * bw);
                __threadfence();
                asm volatile("st.release.gpu.b32 [%0], %1;" :: "l"(&g_flag), "r"(1u) : "memory");
            }
        }
        __syncthreads();
    }

    // ================= phase 1: fill tiles (tf32) + per-CTA row norms =================
#pragma unroll
    for (int i = 0; i < 8; i++) {
        int idx = tid + (i << 8);          // 0..2047
        int r = idx >> 4, f = idx & 15;    // 16 threads per row
        float4 va = *(const float4*)(X + (size_t)(rowBase + r) * DDIM + (f << 2));
        float4 vb = *(const float4*)(X + (size_t)(colBase + r) * DDIM + (f << 2));
        float da = va.x * va.x + va.y * va.y + va.z * va.z + va.w * va.w;
        float db = vb.x * vb.x + vb.y * vb.y + vb.z * vb.z + vb.w * vb.w;
#pragma unroll
        for (int stp = 1; stp <= 8; stp <<= 1) {
            da += __shfl_xor_sync(0xffffffffu, da, stp);
            db += __shfl_xor_sync(0xffffffffu, db, stp);
        }
        if ((lane & 15) == 0) { sqa[r] = da; sqb[r] = db; }
        uint4 ta = { to_tf32(va.x), to_tf32(va.y), to_tf32(va.z), to_tf32(va.w) };
        uint4 tb = { to_tf32(vb.x), to_tf32(vb.y), to_tf32(vb.z), to_tf32(vb.w) };
        *(uint4*)(As + r * LDT + (f << 2)) = ta;
        *(uint4*)(Bs + r * LDT + (f << 2)) = tb;
    }
    __syncthreads();

    // ================= phase 2: tf32 mma.sync Gram =================
    const int g = lane >> 2, t = lane & 3;
    const int warpRow = (wid & 3) << 5;
    const int warpCol = (wid >> 2) << 6;

    float acc[2][8][4];
#pragma unroll
    for (int m = 0; m < 2; m++)
#pragma unroll
        for (int n = 0; n < 8; n++)
#pragma unroll
            for (int j = 0; j < 4; j++) acc[m][n][j] = 0.f;

#pragma unroll
    for (int ks = 0; ks < 8; ks++) {
        const int k0 = ks << 3;
        uint32_t af[2][4], bf[8][2];
#pragma unroll
        for (int m = 0; m < 2; m++) {
            const float* ap = As + (size_t)(warpRow + (m << 4) + g) * LDT + k0 + t;
            af[m][0] = __float_as_uint(ap[0]);
            af[m][1] = __float_as_uint(ap[8 * LDT]);
            af[m][2] = __float_as_uint(ap[4]);
            af[m][3] = __float_as_uint(ap[8 * LDT + 4]);
        }
#pragma unroll
        for (int n = 0; n < 8; n++) {
            const float* bp = Bs + (size_t)(warpCol + (n << 3) + g) * LDT + k0 + t;
            bf[n][0] = __float_as_uint(bp[0]);
            bf[n][1] = __float_as_uint(bp[4]);
        }
#pragma unroll
        for (int m = 0; m < 2; m++)
#pragma unroll
            for (int n = 0; n < 8; n++) {
                asm volatile(
                    "mma.sync.aligned.m16n8k8.row.col.f32.tf32.tf32.f32 "
                    "{%0,%1,%2,%3}, {%4,%5,%6,%7}, {%8,%9}, {%0,%1,%2,%3};"
                    : "+f"(acc[m][n][0]), "+f"(acc[m][n][1]),
                      "+f"(acc[m][n][2]), "+f"(acc[m][n][3])
                    : "r"(af[m][0]), "r"(af[m][1]), "r"(af[m][2]), "r"(af[m][3]),
                      "r"(bf[n][0]), "r"(bf[n][1]));
            }
    }

    // ================= phase 3: wait for g_c (usually already set) =================
    if (tid == 0) {
        unsigned int f;
        do {
            asm volatile("ld.acquire.gpu.b32 %0, [%1];" : "=r"(f) : "l"(&g_flag) : "memory");
        } while (f == 0);
        s_c = g_c;
    }
    __syncthreads();
    const float cc = s_c;

    // ================= phase 4: RBF epilogue + stores =================
#pragma unroll
    for (int m = 0; m < 2; m++) {
        const int r0 = warpRow + (m << 4) + g;       // rows r0, r0+8
        const float sa0 = sqa[r0], sa1 = sqa[r0 + 8];
#pragma unroll
        for (int n = 0; n < 8; n++) {
            const int c0 = warpCol + (n << 3) + (t << 1);
            const float sb0 = sqb[c0], sb1 = sqb[c0 + 1];
            float r[4];
            const float sas[4] = { sa0, sa0, sa1, sa1 };
            const float sbs[4] = { sb0, sb1, sb0, sb1 };
#pragma unroll
            for (int j = 0; j < 4; j++) {
                float l2 = fmaxf(sas[j] + sbs[j] - 2.f * acc[m][n][j], 0.f);
                float e;
                asm("ex2.approx.ftz.f32 %0, %1;" : "=f"(e) : "f"(-l2 * cc));
                float e2 = e * e, e4 = e2 * e2, e8 = e4 * e4, e16 = e8 * e8;
                r[j] = e + e2 + e4 + e8 + e16;
            }
            float* o0 = out + (size_t)(rowBase + r0) * NPTS + colBase + c0;
            float* o1 = out + (size_t)(rowBase + r0 + 8) * NPTS + colBase + c0;
            *(float2*)o0 = make_float2(r[0], r[1]);
            *(float2*)o1 = make_float2(r[2], r[3]);
        }
    }

    // ================= phase 5: last CTA resets counters for next replay =================
    if (tid == 0) {
        int d = atomicAdd(&g_done, 1);
        if (d == (int)(gridDim.x * gridDim.y) - 1) {
            g_arrive = 0;
            g_done = 0;
            asm volatile("st.relaxed.gpu.b32 [%0], %1;" :: "l"(&g_flag), "r"(0u) : "memory");
        }
    }
}

// ---------------- launch ----------------
extern "C" void kernel_launch(void* const* d_in, const int* in_sizes, int n_in,
                              void* d_out, int out_size) {
    const float* X = (const float*)d_in[0];
    float* out = (float*)d_out;

    const int smem_bytes = 2 * 128 * LDT * sizeof(float);   // 69632 dynamic
    cudaFuncSetAttribute(rbf_fused_kernel, cudaFuncAttributeMaxDynamicSharedMemorySize, smem_bytes);

    dim3 grid(NPTS / 128, NPTS / 128);
    rbf_fused_kernel<<<grid, 256, smem_bytes>>>(X, out);
}

// round 6
// speedup vs baseline: 1.1582x; 1.1582x over previous
#include <cuda_runtime.h>
#include <cstdint>

#define NPTS 4096
#define DDIM 64
#define LDT 68      // A/B smem stride (floats), conflict-free fragment loads
#define SLD 132     // staging stride: banks 8t+g -> conflict-free
#define NTILE 32
#define NBLOCKS 528 // 32*33/2 upper-triangular tiles

// ---------------- device scratch (zero-init; counters self-reset) ----------------
__device__ float g_partial_sq[64];
__device__ float g_partial_col[64][64];
__device__ float g_c;
__device__ int   g_arrive = 0;
__device__ int   g_done   = 0;
__device__ unsigned int g_flag = 0;

__device__ __forceinline__ uint32_t to_tf32(float f) {
    uint32_t o; asm("cvt.rna.tf32.f32 %0, %1;" : "=r"(o) : "f"(f)); return o;
}

__global__ __launch_bounds__(256, 2)
void rbf_fused_kernel(const float* __restrict__ X, float* __restrict__ out) {
    extern __shared__ float smem[];
    float* As = smem;                 // [128][LDT] tf32
    float* Bs = smem + 128 * LDT;
    float* stg = smem;                // aliased staging [128][SLD], used post-MMA
    __shared__ float sqa[128], sqb[128];
    __shared__ float red[256];
    __shared__ float colp[8][64];
    __shared__ float s_c;
    __shared__ int   s_last;

    const int tid = threadIdx.x;
    const int wid = tid >> 5, lane = tid & 31;
    const int bid = blockIdx.x;

    // triangular decode: bid -> (bi <= bj)
    int bi = 0, rr = bid;
    while (rr >= NTILE - bi) { rr -= NTILE - bi; bi++; }
    const int bj = bi + rr;
    const int rowBase = bi << 7, colBase = bj << 7;
    const bool offdiag = (bi != bj);

    // ================= phase 0: bandwidth reduction duty (bid < 64) =================
    if (bid < 64) {
        const int rrow = (bid << 6) + (tid >> 2);
        const int q = tid & 3;
        float v[16];
        const float4* p = (const float4*)(X + (size_t)rrow * DDIM + q * 16);
        float s = 0.f;
#pragma unroll
        for (int i = 0; i < 4; i++) {
            float4 f = p[i];
            v[i * 4 + 0] = f.x; v[i * 4 + 1] = f.y; v[i * 4 + 2] = f.z; v[i * 4 + 3] = f.w;
            s += f.x * f.x + f.y * f.y + f.z * f.z + f.w * f.w;
        }
        red[tid] = s;
        __syncthreads();
#pragma unroll
        for (int off = 128; off > 0; off >>= 1) {
            if (tid < off) red[tid] += red[tid + off];
            __syncthreads();
        }
        if (tid == 0) g_partial_sq[bid] = red[0];

#pragma unroll
        for (int stp = 4; stp <= 16; stp <<= 1)
#pragma unroll
            for (int i = 0; i < 16; i++)
                v[i] += __shfl_xor_sync(0xffffffffu, v[i], stp);
        if (lane < 4) {
#pragma unroll
            for (int i = 0; i < 16; i++) colp[wid][lane * 16 + i] = v[i];
        }
        __syncthreads();
        if (tid < 64) {
            float t = 0.f;
#pragma unroll
            for (int w = 0; w < 8; w++) t += colp[w][tid];
            g_partial_col[bid][tid] = t;
        }
        __threadfence();
        if (tid == 0) {
            int r = atomicAdd(&g_arrive, 1);
            s_last = (r == 63);
        }
        __syncthreads();

        if (s_last) {
            if (tid < 64) {
                float cs = 0.f;
#pragma unroll
                for (int b = 0; b < 64; b++) cs += g_partial_col[b][tid];
                red[tid] = cs * cs;
                red[128 + tid] = g_partial_sq[tid];
            }
            __syncthreads();
#pragma unroll
            for (int off = 32; off > 0; off >>= 1) {
                if (tid < off) { red[tid] += red[tid + off]; red[128 + tid] += red[128 + tid + off]; }
                __syncthreads();
            }
            if (tid == 0) {
                // sum(L2) = 2*N*sum(||xi||^2) - 2*||sum xi||^2 (clamp negligible)
                float bwsum = 2.f * (float)NPTS * red[128] - 2.f * red[0];
                float bw = bwsum / ((float)NPTS * (float)(NPTS - 1));
                g_c = 1.4426950408889634f / (4.f * bw);
                __threadfence();
                asm volatile("st.release.gpu.b32 [%0], %1;" :: "l"(&g_flag), "r"(1u) : "memory");
            }
        }
        __syncthreads();
    }

    // ================= phase 1: fill tiles (tf32) + per-CTA row norms =================
#pragma unroll
    for (int i = 0; i < 8; i++) {
        int idx = tid + (i << 8);
        int r = idx >> 4, f = idx & 15;
        float4 va = *(const float4*)(X + (size_t)(rowBase + r) * DDIM + (f << 2));
        float4 vb = *(const float4*)(X + (size_t)(colBase + r) * DDIM + (f << 2));
        float da = va.x * va.x + va.y * va.y + va.z * va.z + va.w * va.w;
        float db = vb.x * vb.x + vb.y * vb.y + vb.z * vb.z + vb.w * vb.w;
#pragma unroll
        for (int stp = 1; stp <= 8; stp <<= 1) {
            da += __shfl_xor_sync(0xffffffffu, da, stp);
            db += __shfl_xor_sync(0xffffffffu, db, stp);
        }
        if ((lane & 15) == 0) { sqa[r] = da; sqb[r] = db; }
        uint4 ta = { to_tf32(va.x), to_tf32(va.y), to_tf32(va.z), to_tf32(va.w) };
        uint4 tb = { to_tf32(vb.x), to_tf32(vb.y), to_tf32(vb.z), to_tf32(vb.w) };
        *(uint4*)(As + r * LDT + (f << 2)) = ta;
        *(uint4*)(Bs + r * LDT + (f << 2)) = tb;
    }
    __syncthreads();

    // ================= phase 2: tf32 mma.sync Gram =================
    const int g = lane >> 2, t = lane & 3;
    const int warpRow = (wid & 3) << 5;
    const int warpCol = (wid >> 2) << 6;

    float acc[2][8][4];
#pragma unroll
    for (int m = 0; m < 2; m++)
#pragma unroll
        for (int n = 0; n < 8; n++)
#pragma unroll
            for (int j = 0; j < 4; j++) acc[m][n][j] = 0.f;

#pragma unroll
    for (int ks = 0; ks < 8; ks++) {
        const int k0 = ks << 3;
        uint32_t af[2][4], bf[8][2];
#pragma unroll
        for (int m = 0; m < 2; m++) {
            const float* ap = As + (size_t)(warpRow + (m << 4) + g) * LDT + k0 + t;
            af[m][0] = __float_as_uint(ap[0]);
            af[m][1] = __float_as_uint(ap[8 * LDT]);
            af[m][2] = __float_as_uint(ap[4]);
            af[m][3] = __float_as_uint(ap[8 * LDT + 4]);
        }
#pragma unroll
        for (int n = 0; n < 8; n++) {
            const float* bp = Bs + (size_t)(warpCol + (n << 3) + g) * LDT + k0 + t;
            bf[n][0] = __float_as_uint(bp[0]);
            bf[n][1] = __float_as_uint(bp[4]);
        }
#pragma unroll
        for (int m = 0; m < 2; m++)
#pragma unroll
            for (int n = 0; n < 8; n++) {
                asm volatile(
                    "mma.sync.aligned.m16n8k8.row.col.f32.tf32.tf32.f32 "
                    "{%0,%1,%2,%3}, {%4,%5,%6,%7}, {%8,%9}, {%0,%1,%2,%3};"
                    : "+f"(acc[m][n][0]), "+f"(acc[m][n][1]),
                      "+f"(acc[m][n][2]), "+f"(acc[m][n][3])
                    : "r"(af[m][0]), "r"(af[m][1]), "r"(af[m][2]), "r"(af[m][3]),
                      "r"(bf[n][0]), "r"(bf[n][1]));
            }
    }

    // ================= phase 3: wait for g_c (usually already set) =================
    if (tid == 0) {
        unsigned int f;
        do {
            asm volatile("ld.acquire.gpu.b32 %0, [%1];" : "=r"(f) : "l"(&g_flag) : "memory");
        } while (f == 0);
        s_c = g_c;
    }
    __syncthreads();   // also guards stg-aliasing of As/Bs

    // ================= phase 4: RBF epilogue + normal store + staging =================
    const float cc = s_c;
    const float c2 = 2.f * cc;
#pragma unroll
    for (int m = 0; m < 2; m++) {
        const int r0 = warpRow + (m << 4) + g;
        const float u0 = -cc * sqa[r0], u1 = -cc * sqa[r0 + 8];
#pragma unroll
        for (int n = 0; n < 8; n++) {
            const int c0 = warpCol + (n << 3) + (t << 1);
            const float v0 = -cc * sqb[c0], v1 = -cc * sqb[c0 + 1];
            const float ws[4] = { u0 + v0, u0 + v1, u1 + v0, u1 + v1 };
            float r[4];
#pragma unroll
            for (int j = 0; j < 4; j++) {
                float y = fminf(fmaf(c2, acc[m][n][j], ws[j]), 0.f);
                float e;
                asm("ex2.approx.ftz.f32 %0, %1;" : "=f"(e) : "f"(y));
                float e2 = e * e, e4 = e2 * e2, e8 = e4 * e4, e16 = e8 * e8;
                r[j] = e + e2 + e4 + e8 + e16;
            }
            float* o0 = out + (size_t)(rowBase + r0) * NPTS + colBase + c0;
            float* o1 = out + (size_t)(rowBase + r0 + 8) * NPTS + colBase + c0;
            *(float2*)o0 = make_float2(r[0], r[1]);
            *(float2*)o1 = make_float2(r[2], r[3]);
            if (offdiag) {
                stg[(c0)     * SLD + r0]     = r[0];
                stg[(c0 + 1) * SLD + r0]     = r[1];
                stg[(c0)     * SLD + r0 + 8] = r[2];
                stg[(c0 + 1) * SLD + r0 + 8] = r[3];
            }
        }
    }

    // ================= phase 5: mirror tile (transposed, coalesced) =================
    if (offdiag) {
        __syncthreads();
        const int c_off = lane >> 3, r_off = (lane & 7) << 2;
#pragma unroll
        for (int i = 0; i < 16; i++) {
            int c = (wid << 4) + ((i & 3) << 2) + c_off;
            int r = ((i >> 2) << 5) + r_off;
            float4 v = *(float4*)&stg[c * SLD + r];
            *(float4*)(out + (size_t)(colBase + c) * NPTS + rowBase + r) = v;
        }
    }

    // ================= phase 6: last CTA resets counters for next replay =================
    if (tid == 0) {
        int d = atomicAdd(&g_done, 1);
        if (d == NBLOCKS - 1) {
            g_arrive = 0;
            g_done = 0;
            asm volatile("st.relaxed.gpu.b32 [%0], %1;" :: "l"(&g_flag), "r"(0u) : "memory");
        }
    }
}

// ---------------- launch ----------------
extern "C" void kernel_launch(void* const* d_in, const int* in_sizes, int n_in,
                              void* d_out, int out_size) {
    const float* X = (const float*)d_in[0];
    float* out = (float*)d_out;

    const int smem_bytes = 2 * 128 * LDT * sizeof(float);   // 69632 >= 128*SLD*4
    cudaFuncSetAttribute(rbf_fused_kernel, cudaFuncAttributeMaxDynamicSharedMemorySize, smem_bytes);

    rbf_fused_kernel<<<NBLOCKS, 256, smem_bytes>>>(X, out);
}

// round 7
// speedup vs baseline: 1.2217x; 1.0548x over previous
#include <cuda_runtime.h>
#include <cstdint>

#define NPTS 4096
#define DDIM 64
#define LDT 68      // A/B smem stride (floats), conflict-free fragment loads
#define SLD 132     // staging stride: conflict-free transpose staging
#define NTILE 32
#define NBLOCKS 272 // pair-tile blocks: sum over bi of (16 - bi/2)

// ---------------- device scratch (zero-init; counters self-reset) ----------------
__device__ float g_partial_sq[64];
__device__ float g_partial_col[64][64];
__device__ float g_c;
__device__ int   g_arrive = 0;
__device__ int   g_done   = 0;
__device__ unsigned int g_flag = 0;

__device__ __forceinline__ uint32_t to_tf32(float f) {
    uint32_t o; asm("cvt.rna.tf32.f32 %0, %1;" : "=r"(o) : "f"(f)); return o;
}

// tf32 mma over one 128x128 tile: As/Bs [128][LDT]
__device__ __forceinline__ void mma_tile(const float* As, const float* Bs,
                                         int warpRow, int warpCol, int g, int t,
                                         float acc[2][8][4]) {
#pragma unroll
    for (int m = 0; m < 2; m++)
#pragma unroll
        for (int n = 0; n < 8; n++)
#pragma unroll
            for (int j = 0; j < 4; j++) acc[m][n][j] = 0.f;
#pragma unroll
    for (int ks = 0; ks < 8; ks++) {
        const int k0 = ks << 3;
        uint32_t af[2][4], bf[8][2];
#pragma unroll
        for (int m = 0; m < 2; m++) {
            const float* ap = As + (size_t)(warpRow + (m << 4) + g) * LDT + k0 + t;
            af[m][0] = __float_as_uint(ap[0]);
            af[m][1] = __float_as_uint(ap[8 * LDT]);
            af[m][2] = __float_as_uint(ap[4]);
            af[m][3] = __float_as_uint(ap[8 * LDT + 4]);
        }
#pragma unroll
        for (int n = 0; n < 8; n++) {
            const float* bp = Bs + (size_t)(warpCol + (n << 3) + g) * LDT + k0 + t;
            bf[n][0] = __float_as_uint(bp[0]);
            bf[n][1] = __float_as_uint(bp[4]);
        }
#pragma unroll
        for (int m = 0; m < 2; m++)
#pragma unroll
            for (int n = 0; n < 8; n++) {
                asm volatile(
                    "mma.sync.aligned.m16n8k8.row.col.f32.tf32.tf32.f32 "
                    "{%0,%1,%2,%3}, {%4,%5,%6,%7}, {%8,%9}, {%0,%1,%2,%3};"
                    : "+f"(acc[m][n][0]), "+f"(acc[m][n][1]),
                      "+f"(acc[m][n][2]), "+f"(acc[m][n][3])
                    : "r"(af[m][0]), "r"(af[m][1]), "r"(af[m][2]), "r"(af[m][3]),
                      "r"(bf[n][0]), "r"(bf[n][1]));
            }
    }
}

// epilogue: direct stores (+ optional transpose staging)
__device__ __forceinline__ void epilogue_tile(float acc[2][8][4],
                                              const float* sqa, const float* sqb,
                                              float cc, float* out,
                                              int rowBase, int colBase,
                                              int warpRow, int warpCol, int g, int t,
                                              bool stage, float* stg) {
    const float c2 = 2.f * cc;
#pragma unroll
    for (int m = 0; m < 2; m++) {
        const int r0 = warpRow + (m << 4) + g;
        const float u0 = -cc * sqa[r0], u1 = -cc * sqa[r0 + 8];
#pragma unroll
        for (int n = 0; n < 8; n++) {
            const int c0 = warpCol + (n << 3) + (t << 1);
            const float v0 = -cc * sqb[c0], v1 = -cc * sqb[c0 + 1];
            const float ws[4] = { u0 + v0, u0 + v1, u1 + v0, u1 + v1 };
            float r[4];
#pragma unroll
            for (int j = 0; j < 4; j++) {
                float y = fminf(fmaf(c2, acc[m][n][j], ws[j]), 0.f);
                float e;
                asm("ex2.approx.ftz.f32 %0, %1;" : "=f"(e) : "f"(y));
                float e2 = e * e, e4 = e2 * e2, e8 = e4 * e4, e16 = e8 * e8;
                r[j] = e + e2 + e4 + e8 + e16;
            }
            float* o0 = out + (size_t)(rowBase + r0) * NPTS + colBase + c0;
            float* o1 = out + (size_t)(rowBase + r0 + 8) * NPTS + colBase + c0;
            *(float2*)o0 = make_float2(r[0], r[1]);
            *(float2*)o1 = make_float2(r[2], r[3]);
            if (stage) {
                stg[(c0)     * SLD + r0]     = r[0];
                stg[(c0 + 1) * SLD + r0]     = r[1];
                stg[(c0)     * SLD + r0 + 8] = r[2];
                stg[(c0 + 1) * SLD + r0 + 8] = r[3];
            }
        }
    }
}

__device__ __forceinline__ void mirror_tile(const float* stg, float* out,
                                            int rowBase, int colBase,
                                            int wid, int lane) {
    const int c_off = lane >> 3, r_off = (lane & 7) << 2;
#pragma unroll
    for (int i = 0; i < 16; i++) {
        int c = (wid << 4) + ((i & 3) << 2) + c_off;
        int r = ((i >> 2) << 5) + r_off;
        float4 v = *(const float4*)&stg[c * SLD + r];
        *(float4*)(out + (size_t)(colBase + c) * NPTS + rowBase + r) = v;
    }
}

__global__ __launch_bounds__(256, 2)
void rbf_fused_kernel(const float* __restrict__ X, float* __restrict__ out) {
    extern __shared__ float smem[];
    float* As  = smem;                  // [128][LDT]
    float* B1s = smem + 128 * LDT;
    float* B2s = smem + 2 * 128 * LDT;
    float* stg = smem + 128 * LDT;      // aliases B1s+B2s (128*SLD <= 2*128*LDT)
    __shared__ float sqa[128], sqb1[128], sqb2[128];
    __shared__ float red[256];
    __shared__ float colp[8][64];
    __shared__ float s_c;
    __shared__ int   s_last;

    const int tid = threadIdx.x;
    const int wid = tid >> 5, lane = tid & 31;
    const int bid = blockIdx.x;

    // pair-tile decode: bid -> (bi, p); tiles (bi, 2p) [if valid] and (bi, 2p+1)
    int bi = 0, rr = bid;
    while (rr >= 16 - (bi >> 1)) { rr -= 16 - (bi >> 1); bi++; }
    const int p = (bi >> 1) + rr;
    const bool two = (2 * p >= bi);
    const int bj1 = two ? 2 * p : 2 * p + 1;
    const int bj2 = 2 * p + 1;
    const bool diag1 = (bj1 == bi);
    const int rowBase = bi << 7, colBase1 = bj1 << 7, colBase2 = bj2 << 7;

    // ================= phase 0: bandwidth reduction duty (bid < 64) =================
    if (bid < 64) {
        const int rrow = (bid << 6) + (tid >> 2);
        const int q = tid & 3;
        float v[16];
        const float4* pp = (const float4*)(X + (size_t)rrow * DDIM + q * 16);
        float s = 0.f;
#pragma unroll
        for (int i = 0; i < 4; i++) {
            float4 f = pp[i];
            v[i * 4 + 0] = f.x; v[i * 4 + 1] = f.y; v[i * 4 + 2] = f.z; v[i * 4 + 3] = f.w;
            s += f.x * f.x + f.y * f.y + f.z * f.z + f.w * f.w;
        }
        red[tid] = s;
        __syncthreads();
#pragma unroll
        for (int off = 128; off > 0; off >>= 1) {
            if (tid < off) red[tid] += red[tid + off];
            __syncthreads();
        }
        if (tid == 0) g_partial_sq[bid] = red[0];
#pragma unroll
        for (int stp = 4; stp <= 16; stp <<= 1)
#pragma unroll
            for (int i = 0; i < 16; i++)
                v[i] += __shfl_xor_sync(0xffffffffu, v[i], stp);
        if (lane < 4) {
#pragma unroll
            for (int i = 0; i < 16; i++) colp[wid][lane * 16 + i] = v[i];
        }
        __syncthreads();
        if (tid < 64) {
            float t = 0.f;
#pragma unroll
            for (int w = 0; w < 8; w++) t += colp[w][tid];
            g_partial_col[bid][tid] = t;
        }
        __threadfence();
        if (tid == 0) {
            int r = atomicAdd(&g_arrive, 1);
            s_last = (r == 63);
        }
        __syncthreads();
        if (s_last) {
            if (tid < 64) {
                float cs = 0.f;
#pragma unroll
                for (int b = 0; b < 64; b++) cs += g_partial_col[b][tid];
                red[tid] = cs * cs;
                red[128 + tid] = g_partial_sq[tid];
            }
            __syncthreads();
#pragma unroll
            for (int off = 32; off > 0; off >>= 1) {
                if (tid < off) { red[tid] += red[tid + off]; red[128 + tid] += red[128 + tid + off]; }
                __syncthreads();
            }
            if (tid == 0) {
                // sum(L2) = 2*N*sum(||xi||^2) - 2*||sum xi||^2 (clamp negligible)
                float bwsum = 2.f * (float)NPTS * red[128] - 2.f * red[0];
                float bw = bwsum / ((float)NPTS * (float)(NPTS - 1));
                g_c = 1.4426950408889634f / (4.f * bw);
                __threadfence();
                asm volatile("st.release.gpu.b32 [%0], %1;" :: "l"(&g_flag), "r"(1u) : "memory");
            }
        }
        __syncthreads();
    }

    // ================= phase 1: fill A + B1 tiles (tf32) + norms =================
#pragma unroll
    for (int i = 0; i < 8; i++) {
        int idx = tid + (i << 8);
        int r = idx >> 4, f = idx & 15;
        float4 va = *(const float4*)(X + (size_t)(rowBase + r) * DDIM + (f << 2));
        float4 vb = *(const float4*)(X + (size_t)(colBase1 + r) * DDIM + (f << 2));
        float da = va.x * va.x + va.y * va.y + va.z * va.z + va.w * va.w;
        float db = vb.x * vb.x + vb.y * vb.y + vb.z * vb.z + vb.w * vb.w;
#pragma unroll
        for (int stp = 1; stp <= 8; stp <<= 1) {
            da += __shfl_xor_sync(0xffffffffu, da, stp);
            db += __shfl_xor_sync(0xffffffffu, db, stp);
        }
        if ((lane & 15) == 0) { sqa[r] = da; sqb1[r] = db; }
        uint4 ta = { to_tf32(va.x), to_tf32(va.y), to_tf32(va.z), to_tf32(va.w) };
        uint4 tb = { to_tf32(vb.x), to_tf32(vb.y), to_tf32(vb.z), to_tf32(vb.w) };
        *(uint4*)(As + r * LDT + (f << 2)) = ta;
        *(uint4*)(B1s + r * LDT + (f << 2)) = tb;
    }
    __syncthreads();

    // ================= phase 2: MMA tile 1 =================
    const int g = lane >> 2, t = lane & 3;
    const int warpRow = (wid & 3) << 5;
    const int warpCol = (wid >> 2) << 6;

    float acc[2][8][4];
    mma_tile(As, B1s, warpRow, warpCol, g, t, acc);

    // prefetch B2 into registers (latency hides under spin + epilogue1)
    float4 pb2[8];
    if (two) {
#pragma unroll
        for (int i = 0; i < 8; i++) {
            int idx = tid + (i << 8);
            int r = idx >> 4, f = idx & 15;
            pb2[i] = *(const float4*)(X + (size_t)(colBase2 + r) * DDIM + (f << 2));
        }
    }

    // ================= phase 3: wait for g_c (usually already set) =================
    if (tid == 0) {
        unsigned int f;
        do {
            asm volatile("ld.acquire.gpu.b32 %0, [%1];" : "=r"(f) : "l"(&g_flag) : "memory");
        } while (f == 0);
        s_c = g_c;
    }
    __syncthreads();   // also: all MMA1 B1s/As reads complete before stg writes
    const float cc = s_c;

    // ================= phase 4: epilogue tile 1 (+ mirror if offdiag) =================
    epilogue_tile(acc, sqa, sqb1, cc, out, rowBase, colBase1,
                  warpRow, warpCol, g, t, !diag1, stg);
    if (!diag1) {
        __syncthreads();
        mirror_tile(stg, out, rowBase, colBase1, wid, lane);
    }

    // ================= phase 5: tile 2 =================
    if (two) {
        __syncthreads();   // mirror1 stg reads done before B2s overwrite
#pragma unroll
        for (int i = 0; i < 8; i++) {
            int idx = tid + (i << 8);
            int r = idx >> 4, f = idx & 15;
            float4 vb = pb2[i];
            float db = vb.x * vb.x + vb.y * vb.y + vb.z * vb.z + vb.w * vb.w;
#pragma unroll
            for (int stp = 1; stp <= 8; stp <<= 1)
                db += __shfl_xor_sync(0xffffffffu, db, stp);
            if ((lane & 15) == 0) sqb2[r] = db;
            uint4 tb = { to_tf32(vb.x), to_tf32(vb.y), to_tf32(vb.z), to_tf32(vb.w) };
            *(uint4*)(B2s + r * LDT + (f << 2)) = tb;
        }
        __syncthreads();

        mma_tile(As, B2s, warpRow, warpCol, g, t, acc);
        __syncthreads();   // all B2s reads complete before stg writes

        epilogue_tile(acc, sqa, sqb2, cc, out, rowBase, colBase2,
                      warpRow, warpCol, g, t, true, stg);
        __syncthreads();
        mirror_tile(stg, out, rowBase, colBase2, wid, lane);
    }

    // ================= phase 6: last CTA resets counters for next replay =================
    if (tid == 0) {
        int d = atomicAdd(&g_done, 1);
        if (d == NBLOCKS - 1) {
            g_arrive = 0;
            g_done = 0;
            asm volatile("st.relaxed.gpu.b32 [%0], %1;" :: "l"(&g_flag), "r"(0u) : "memory");
        }
    }
}

// ---------------- launch ----------------
extern "C" void kernel_launch(void* const* d_in, const int* in_sizes, int n_in,
                              void* d_out, int out_size) {
    const float* X = (const float*)d_in[0];
    float* out = (float*)d_out;

    const int smem_bytes = 3 * 128 * LDT * sizeof(float);   // 104448
    cudaFuncSetAttribute(rbf_fused_kernel, cudaFuncAttributeMaxDynamicSharedMemorySize, smem_bytes);

    rbf_fused_kernel<<<NBLOCKS, 256, smem_bytes>>>(X, out);
}